// round 8
// baseline (speedup 1.0000x reference)
#include <cuda_runtime.h>
#include <cstdint>

#define T_TOK 8192
#define D_DIM 1024
#define E_EXP 8
#define F_DIM 2048
#define NSLOT (2 * T_TOK)

// ---------------- device-global scratch ----------------
__device__ int   g_cnt[E_EXP];
__device__ int   g_list[E_EXP * T_TOK];
__device__ float g_probs[NSLOT];
__device__ float g_Hs[(size_t)NSLOT * F_DIM];  // silu(x@w1), exact fp32
__device__ float g_H[(size_t)NSLOT * F_DIM];   // tf32-rounded silu*C3
__device__ float g_Y[(size_t)NSLOT * D_DIM];

// ---------------- helpers ----------------
__device__ __forceinline__ uint32_t smem_u32(const void* p) {
    uint32_t a;
    asm("{ .reg .u64 t; cvta.to.shared.u64 t, %1; cvt.u32.u64 %0, t; }" : "=r"(a) : "l"(p));
    return a;
}
__device__ __forceinline__ float to_tf32(float x) {
    uint32_t r;
    asm("cvt.rna.tf32.f32 %0, %1;" : "=r"(r) : "f"(x));
    return __uint_as_float(r);
}
__device__ __forceinline__ uint32_t lds_tf32(const float* p) {
    uint32_t r;
    asm("cvt.rna.tf32.f32 %0, %1;" : "=r"(r) : "f"(*p));
    return r;
}
#define CP16(dst, src) asm volatile("cp.async.cg.shared.global [%0], [%1], 16;" :: "r"(dst), "l"(src))
#define CP_COMMIT()    asm volatile("cp.async.commit_group;")
#define CP_WAIT1()     asm volatile("cp.async.wait_group 1;")

#define MMA_TF32(c, a, b)                                                          \
    asm volatile("mma.sync.aligned.m16n8k8.row.col.f32.tf32.tf32.f32 "             \
                 "{%0,%1,%2,%3}, {%4,%5,%6,%7}, {%8,%9}, {%0,%1,%2,%3};"           \
                 : "+f"((c)[0]), "+f"((c)[1]), "+f"((c)[2]), "+f"((c)[3])          \
                 : "r"((a)[0]), "r"((a)[1]), "r"((a)[2]), "r"((a)[3]),             \
                   "r"((b)[0]), "r"((b)[1]))

// smem strides (floats): A rows padded to 36 (144B), B rows padded to 136 (544B)
#define AST 36
#define BST 136
#define A_BYTES (128 * AST * 4)   // 18432
#define B_BYTES (32 * BST * 4)    // 17408

// ---------------- init ----------------
__global__ void init_kernel() {
    if (threadIdx.x < E_EXP) g_cnt[threadIdx.x] = 0;
}

// ---------------- gating (proven) ----------------
__global__ void __launch_bounds__(256) gate_kernel(const float* __restrict__ x,
                                                   const float* __restrict__ wg) {
    __shared__ float swg[E_EXP][D_DIM];
    int tid = threadIdx.x;
    for (int i = tid; i < D_DIM * E_EXP; i += 256) {
        int d = i >> 3, e = i & 7;
        swg[e][d] = wg[i];
    }
    __syncthreads();

    int warp = tid >> 5, lane = tid & 31;
    int t = blockIdx.x * 8 + warp;
    const float* xr = x + (size_t)t * D_DIM;

    float acc[E_EXP];
#pragma unroll
    for (int e = 0; e < E_EXP; e++) acc[e] = 0.f;
    for (int d = lane; d < D_DIM; d += 32) {
        float xv = xr[d];
#pragma unroll
        for (int e = 0; e < E_EXP; e++) acc[e] = fmaf(xv, swg[e][d], acc[e]);
    }
#pragma unroll
    for (int e = 0; e < E_EXP; e++)
#pragma unroll
        for (int o = 16; o > 0; o >>= 1)
            acc[e] += __shfl_xor_sync(0xffffffffu, acc[e], o);

    if (lane == 0) {
        int e0 = 0; float l0 = acc[0];
#pragma unroll
        for (int e = 1; e < E_EXP; e++) if (acc[e] > l0) { l0 = acc[e]; e0 = e; }
        int e1 = -1; float l1 = -3.0e38f;
#pragma unroll
        for (int e = 0; e < E_EXP; e++) {
            if (e == e0) continue;
            if (acc[e] > l1) { l1 = acc[e]; e1 = e; }
        }
        float ex  = __expf(l1 - l0);
        float inv = 1.f / (1.f + ex);
        g_probs[2 * t]     = inv;
        g_probs[2 * t + 1] = ex * inv;
        int p0 = atomicAdd(&g_cnt[e0], 1);
        g_list[e0 * T_TOK + p0] = 2 * t;
        int p1 = atomicAdd(&g_cnt[e1], 1);
        g_list[e1 * T_TOK + p1] = 2 * t + 1;
    }
}

// ============= GEMM1a: g_Hs = silu(gather(x) @ w1)  (gemm2-proven config) =====
__global__ void __launch_bounds__(256, 2) gemm1a_kernel(const float* __restrict__ x,
                                                        const float* __restrict__ w1) {
    int e   = blockIdx.z;
    int n_e = g_cnt[e];
    int m0  = blockIdx.x * 128;
    if (m0 >= n_e) return;
    int f0  = blockIdx.y * 128;

    extern __shared__ char smem[];
    int* slots = (int*)smem;
    uint32_t sb = smem_u32(smem);
    int tid = threadIdx.x, wid = tid >> 5, lane = tid & 31;

    if (tid < 128) {
        int m = m0 + tid;
        slots[tid] = g_list[e * T_TOK + (m < n_e ? m : m0)];
    }
    __syncthreads();

    const float* W = w1 + (size_t)e * D_DIM * F_DIM + f0;

    auto issue = [&](int ci, int s) {
        int k0 = ci * 32;
        uint32_t base = sb + 1024 + s * (A_BYTES + B_BYTES);
#pragma unroll
        for (int it = 0; it < 4; it++) {
            int idx = it * 256 + tid;
            int row = idx >> 3, kq = idx & 7;
            const float* src = x + (size_t)(slots[row] >> 1) * D_DIM + k0 + kq * 4;
            CP16(base + row * 144 + kq * 16, src);
        }
        uint32_t bb = base + A_BYTES;
#pragma unroll
        for (int it = 0; it < 4; it++) {
            int idx = it * 256 + tid;
            int kr = idx >> 5, nq = idx & 31;
            CP16(bb + kr * 544 + nq * 16, W + (size_t)(k0 + kr) * F_DIM + nq * 4);
        }
        CP_COMMIT();
    };

    issue(0, 0);
    issue(1, 1);

    int g = lane >> 2, t = lane & 3;
    int m0w = (wid & 1) * 64, n0w = (wid >> 1) * 32;

    float c[4][4][4];
#pragma unroll
    for (int a = 0; a < 4; a++)
#pragma unroll
        for (int b = 0; b < 4; b++)
#pragma unroll
            for (int r = 0; r < 4; r++) c[a][b][r] = 0.f;

    const int NCH = D_DIM / 32;  // 32
    int cur = 0, ibuf = 2;
    for (int ci = 0; ci < NCH; ci++) {
        CP_WAIT1();
        __syncthreads();
        if (ci + 2 < NCH) issue(ci + 2, ibuf); else CP_COMMIT();
        if (++ibuf == 3) ibuf = 0;

        const float* As = (const float*)(smem + 1024 + cur * (A_BYTES + B_BYTES));
        const float* Bs = As + A_BYTES / 4;
        if (++cur == 3) cur = 0;

#pragma unroll
        for (int kk = 0; kk < 4; kk++) {
            uint32_t af[4][4], bf[4][2];
#pragma unroll
            for (int mf = 0; mf < 4; mf++) {
                const float* ap = As + (m0w + mf * 16 + g) * AST + kk * 8 + t;
                af[mf][0] = lds_tf32(ap);
                af[mf][1] = lds_tf32(ap + 8 * AST);
                af[mf][2] = lds_tf32(ap + 4);
                af[mf][3] = lds_tf32(ap + 8 * AST + 4);
            }
#pragma unroll
            for (int nf = 0; nf < 4; nf++) {
                const float* bp = Bs + (kk * 8 + t) * BST + n0w + nf * 8 + g;
                bf[nf][0] = lds_tf32(bp);
                bf[nf][1] = lds_tf32(bp + 4 * BST);
            }
#pragma unroll
            for (int mf = 0; mf < 4; mf++)
#pragma unroll
                for (int nf = 0; nf < 4; nf++)
                    MMA_TF32(c[mf][nf], af[mf], bf[nf]);
        }
    }

    // epilogue: store silu(c) exact fp32
#pragma unroll
    for (int mf = 0; mf < 4; mf++) {
#pragma unroll
        for (int half = 0; half < 2; half++) {
            int row = m0w + mf * 16 + g + 8 * half;
            if (m0 + row >= n_e) continue;
            float* hp = g_Hs + (size_t)slots[row] * F_DIM + f0;
#pragma unroll
            for (int nf = 0; nf < 4; nf++) {
                float v0 = c[mf][nf][2 * half + 0];
                float v1 = c[mf][nf][2 * half + 1];
                float2 o;
                o.x = v0 / (1.f + __expf(-v0));
                o.y = v1 / (1.f + __expf(-v1));
                *(float2*)(hp + n0w + nf * 8 + 2 * t) = o;
            }
        }
    }
}

// ============= GEMM1b: g_H = tf32(g_Hs * (gather(x) @ w3)) ====================
__global__ void __launch_bounds__(256, 2) gemm1b_kernel(const float* __restrict__ x,
                                                        const float* __restrict__ w3) {
    int e   = blockIdx.z;
    int n_e = g_cnt[e];
    int m0  = blockIdx.x * 128;
    if (m0 >= n_e) return;
    int f0  = blockIdx.y * 128;

    extern __shared__ char smem[];
    int* slots = (int*)smem;
    uint32_t sb = smem_u32(smem);
    int tid = threadIdx.x, wid = tid >> 5, lane = tid & 31;

    if (tid < 128) {
        int m = m0 + tid;
        slots[tid] = g_list[e * T_TOK + (m < n_e ? m : m0)];
    }
    __syncthreads();

    const float* W = w3 + (size_t)e * D_DIM * F_DIM + f0;

    auto issue = [&](int ci, int s) {
        int k0 = ci * 32;
        uint32_t base = sb + 1024 + s * (A_BYTES + B_BYTES);
#pragma unroll
        for (int it = 0; it < 4; it++) {
            int idx = it * 256 + tid;
            int row = idx >> 3, kq = idx & 7;
            const float* src = x + (size_t)(slots[row] >> 1) * D_DIM + k0 + kq * 4;
            CP16(base + row * 144 + kq * 16, src);
        }
        uint32_t bb = base + A_BYTES;
#pragma unroll
        for (int it = 0; it < 4; it++) {
            int idx = it * 256 + tid;
            int kr = idx >> 5, nq = idx & 31;
            CP16(bb + kr * 544 + nq * 16, W + (size_t)(k0 + kr) * F_DIM + nq * 4);
        }
        CP_COMMIT();
    };

    issue(0, 0);
    issue(1, 1);

    int g = lane >> 2, t = lane & 3;
    int m0w = (wid & 1) * 64, n0w = (wid >> 1) * 32;

    float c[4][4][4];
#pragma unroll
    for (int a = 0; a < 4; a++)
#pragma unroll
        for (int b = 0; b < 4; b++)
#pragma unroll
            for (int r = 0; r < 4; r++) c[a][b][r] = 0.f;

    const int NCH = D_DIM / 32;  // 32
    int cur = 0, ibuf = 2;
    for (int ci = 0; ci < NCH; ci++) {
        CP_WAIT1();
        __syncthreads();
        if (ci + 2 < NCH) issue(ci + 2, ibuf); else CP_COMMIT();
        if (++ibuf == 3) ibuf = 0;

        const float* As = (const float*)(smem + 1024 + cur * (A_BYTES + B_BYTES));
        const float* Bs = As + A_BYTES / 4;
        if (++cur == 3) cur = 0;

#pragma unroll
        for (int kk = 0; kk < 4; kk++) {
            uint32_t af[4][4], bf[4][2];
#pragma unroll
            for (int mf = 0; mf < 4; mf++) {
                const float* ap = As + (m0w + mf * 16 + g) * AST + kk * 8 + t;
                af[mf][0] = lds_tf32(ap);
                af[mf][1] = lds_tf32(ap + 8 * AST);
                af[mf][2] = lds_tf32(ap + 4);
                af[mf][3] = lds_tf32(ap + 8 * AST + 4);
            }
#pragma unroll
            for (int nf = 0; nf < 4; nf++) {
                const float* bp = Bs + (kk * 8 + t) * BST + n0w + nf * 8 + g;
                bf[nf][0] = lds_tf32(bp);
                bf[nf][1] = lds_tf32(bp + 4 * BST);
            }
#pragma unroll
            for (int mf = 0; mf < 4; mf++)
#pragma unroll
                for (int nf = 0; nf < 4; nf++)
                    MMA_TF32(c[mf][nf], af[mf], bf[nf]);
        }
    }

    // epilogue: H = rna_tf32(silu_stored * c3)
#pragma unroll
    for (int mf = 0; mf < 4; mf++) {
#pragma unroll
        for (int half = 0; half < 2; half++) {
            int row = m0w + mf * 16 + g + 8 * half;
            if (m0 + row >= n_e) continue;
            const float* sp = g_Hs + (size_t)slots[row] * F_DIM + f0;
            float* hp = g_H + (size_t)slots[row] * F_DIM + f0;
#pragma unroll
            for (int nf = 0; nf < 4; nf++) {
                float2 s = *(const float2*)(sp + n0w + nf * 8 + 2 * t);
                float2 o;
                o.x = to_tf32(s.x * c[mf][nf][2 * half + 0]);
                o.y = to_tf32(s.y * c[mf][nf][2 * half + 1]);
                *(float2*)(hp + n0w + nf * 8 + 2 * t) = o;
            }
        }
    }
}

// ======================= GEMM2: Y = H @ w2 (R6 proven, untouched) =============
__global__ void __launch_bounds__(256, 2) gemm2_kernel(const float* __restrict__ w2) {
    int e   = blockIdx.z;
    int n_e = g_cnt[e];
    int m0  = blockIdx.x * 128;
    if (m0 >= n_e) return;
    int n0  = blockIdx.y * 128;

    extern __shared__ char smem[];
    int* slots = (int*)smem;
    uint32_t sb = smem_u32(smem);
    int tid = threadIdx.x, wid = tid >> 5, lane = tid & 31;

    if (tid < 128) {
        int m = m0 + tid;
        slots[tid] = g_list[e * T_TOK + (m < n_e ? m : m0)];
    }
    __syncthreads();

    const float* W2 = w2 + (size_t)e * F_DIM * D_DIM + n0;

    auto issue = [&](int ci, int s) {
        int k0 = ci * 32;
        uint32_t base = sb + 1024 + s * (A_BYTES + B_BYTES);
#pragma unroll
        for (int it = 0; it < 4; it++) {
            int idx = it * 256 + tid;
            int row = idx >> 3, kq = idx & 7;
            const float* src = g_H + (size_t)slots[row] * F_DIM + k0 + kq * 4;
            CP16(base + row * 144 + kq * 16, src);
        }
        uint32_t bb = base + A_BYTES;
#pragma unroll
        for (int it = 0; it < 4; it++) {
            int idx = it * 256 + tid;
            int kr = idx >> 5, nq = idx & 31;
            CP16(bb + kr * 544 + nq * 16, W2 + (size_t)(k0 + kr) * D_DIM + nq * 4);
        }
        CP_COMMIT();
    };

    issue(0, 0);
    issue(1, 1);

    int g = lane >> 2, t = lane & 3;
    int m0w = (wid & 1) * 64, n0w = (wid >> 1) * 32;

    float c[4][4][4];
#pragma unroll
    for (int a = 0; a < 4; a++)
#pragma unroll
        for (int b = 0; b < 4; b++)
#pragma unroll
            for (int r = 0; r < 4; r++) c[a][b][r] = 0.f;

    const int NCH = F_DIM / 32;  // 64
    int cur = 0, ibuf = 2;
    for (int ci = 0; ci < NCH; ci++) {
        CP_WAIT1();
        __syncthreads();
        if (ci + 2 < NCH) issue(ci + 2, ibuf); else CP_COMMIT();
        if (++ibuf == 3) ibuf = 0;

        const float* As = (const float*)(smem + 1024 + cur * (A_BYTES + B_BYTES));
        const float* Bs = As + A_BYTES / 4;
        if (++cur == 3) cur = 0;

#pragma unroll
        for (int kk = 0; kk < 4; kk++) {
            uint32_t af[4][4], bf[4][2];
#pragma unroll
            for (int mf = 0; mf < 4; mf++) {
                const float* ap = As + (m0w + mf * 16 + g) * AST + kk * 8 + t;
                af[mf][0] = __float_as_uint(ap[0]);
                af[mf][1] = __float_as_uint(ap[8 * AST]);
                af[mf][2] = __float_as_uint(ap[4]);
                af[mf][3] = __float_as_uint(ap[8 * AST + 4]);
            }
#pragma unroll
            for (int nf = 0; nf < 4; nf++) {
                const float* bp = Bs + (kk * 8 + t) * BST + n0w + nf * 8 + g;
                bf[nf][0] = lds_tf32(bp);
                bf[nf][1] = lds_tf32(bp + 4 * BST);
            }
#pragma unroll
            for (int mf = 0; mf < 4; mf++)
#pragma unroll
                for (int nf = 0; nf < 4; nf++)
                    MMA_TF32(c[mf][nf], af[mf], bf[nf]);
        }
    }

#pragma unroll
    for (int mf = 0; mf < 4; mf++) {
#pragma unroll
        for (int half = 0; half < 2; half++) {
            int row = m0w + mf * 16 + g + 8 * half;
            if (m0 + row >= n_e) continue;
            float* yp = g_Y + (size_t)slots[row] * D_DIM + n0;
#pragma unroll
            for (int nf = 0; nf < 4; nf++) {
                float2 o;
                o.x = c[mf][nf][2 * half + 0];
                o.y = c[mf][nf][2 * half + 1];
                *(float2*)(yp + n0w + nf * 8 + 2 * t) = o;
            }
        }
    }
}

// ---------------- combine ----------------
__global__ void __launch_bounds__(256) combine_kernel(float* __restrict__ out) {
    int idx = blockIdx.x * 256 + threadIdx.x;
    int t   = idx / (D_DIM / 4);
    int d4  = idx % (D_DIM / 4);
    float p0 = g_probs[2 * t], p1 = g_probs[2 * t + 1];
    const float4* y0 = (const float4*)(g_Y + (size_t)(2 * t) * D_DIM) + d4;
    const float4* y1 = (const float4*)(g_Y + (size_t)(2 * t + 1) * D_DIM) + d4;
    float4 a = *y0, b = *y1, o;
    o.x = p0 * a.x + p1 * b.x;
    o.y = p0 * a.y + p1 * b.y;
    o.z = p0 * a.z + p1 * b.z;
    o.w = p0 * a.w + p1 * b.w;
    *((float4*)(out + (size_t)t * D_DIM) + d4) = o;
}

// ---------------- launch ----------------
extern "C" void kernel_launch(void* const* d_in, const int* in_sizes, int n_in,
                              void* d_out, int out_size) {
    const float* x  = (const float*)d_in[0];
    const float* wg = (const float*)d_in[1];
    const float* w1 = (const float*)d_in[2];
    const float* w3 = (const float*)d_in[3];
    const float* w2 = (const float*)d_in[4];
    float* out = (float*)d_out;

    const int SMEM_G = 1024 + 3 * (A_BYTES + B_BYTES);  // 108544
    cudaFuncSetAttribute(gemm1a_kernel, cudaFuncAttributeMaxDynamicSharedMemorySize, SMEM_G);
    cudaFuncSetAttribute(gemm1b_kernel, cudaFuncAttributeMaxDynamicSharedMemorySize, SMEM_G);
    cudaFuncSetAttribute(gemm2_kernel,  cudaFuncAttributeMaxDynamicSharedMemorySize, SMEM_G);

    init_kernel<<<1, 32>>>();
    gate_kernel<<<T_TOK / 8, 256>>>(x, wg);
    gemm1a_kernel<<<dim3(T_TOK / 128, F_DIM / 128, E_EXP), 256, SMEM_G>>>(x, w1);
    gemm1b_kernel<<<dim3(T_TOK / 128, F_DIM / 128, E_EXP), 256, SMEM_G>>>(x, w3);
    gemm2_kernel<<<dim3(T_TOK / 128, D_DIM / 128, E_EXP), 256, SMEM_G>>>(w2);
    combine_kernel<<<(T_TOK * D_DIM / 4) / 256, 256>>>(out);
}

// round 9
// speedup vs baseline: 1.0669x; 1.0669x over previous
#include <cuda_runtime.h>
#include <cstdint>

#define T_TOK 8192
#define D_DIM 1024
#define E_EXP 8
#define F_DIM 2048
#define NSLOT (2 * T_TOK)

// ---------------- device-global scratch ----------------
__device__ int   g_cnt[E_EXP];
__device__ int   g_list[E_EXP * T_TOK];
__device__ float g_probs[NSLOT];
__device__ float g_xr[(size_t)T_TOK * D_DIM];  // tf32-rounded x
__device__ float g_Hs[(size_t)NSLOT * F_DIM];  // silu(x@w1), exact fp32
__device__ float g_H[(size_t)NSLOT * F_DIM];   // tf32-rounded silu*C3
__device__ float g_Y[(size_t)NSLOT * D_DIM];

// ---------------- helpers ----------------
__device__ __forceinline__ uint32_t smem_u32(const void* p) {
    uint32_t a;
    asm("{ .reg .u64 t; cvta.to.shared.u64 t, %1; cvt.u32.u64 %0, t; }" : "=r"(a) : "l"(p));
    return a;
}
__device__ __forceinline__ float to_tf32(float x) {
    uint32_t r;
    asm("cvt.rna.tf32.f32 %0, %1;" : "=r"(r) : "f"(x));
    return __uint_as_float(r);
}
__device__ __forceinline__ uint32_t lds_tf32(const float* p) {
    uint32_t r;
    asm("cvt.rna.tf32.f32 %0, %1;" : "=r"(r) : "f"(*p));
    return r;
}
#define CP16(dst, src) asm volatile("cp.async.cg.shared.global [%0], [%1], 16;" :: "r"(dst), "l"(src))
#define CP_COMMIT()    asm volatile("cp.async.commit_group;")
#define CP_WAIT1()     asm volatile("cp.async.wait_group 1;")

#define MMA_TF32(c, a, b)                                                          \
    asm volatile("mma.sync.aligned.m16n8k8.row.col.f32.tf32.tf32.f32 "             \
                 "{%0,%1,%2,%3}, {%4,%5,%6,%7}, {%8,%9}, {%0,%1,%2,%3};"           \
                 : "+f"((c)[0]), "+f"((c)[1]), "+f"((c)[2]), "+f"((c)[3])          \
                 : "r"((a)[0]), "r"((a)[1]), "r"((a)[2]), "r"((a)[3]),             \
                   "r"((b)[0]), "r"((b)[1]))

// smem strides (floats): A rows padded to 36 (144B), B rows padded to 136 (544B)
#define AST 36
#define BST 136
#define A_BYTES (128 * AST * 4)   // 18432
#define B_BYTES (32 * BST * 4)    // 17408

// ---------------- init ----------------
__global__ void init_kernel() {
    if (threadIdx.x < E_EXP) g_cnt[threadIdx.x] = 0;
}

// ---------------- pre-round x to tf32 (32 MB only) ----------------
__global__ void __launch_bounds__(256) round_x_kernel(const float4* __restrict__ x,
                                                      float4* __restrict__ xr) {
    int i = blockIdx.x * 256 + threadIdx.x;
    const int n4 = T_TOK * D_DIM / 4;
    int stride = gridDim.x * 256;
    for (; i < n4; i += stride) {
        float4 v = x[i];
        v.x = to_tf32(v.x); v.y = to_tf32(v.y);
        v.z = to_tf32(v.z); v.w = to_tf32(v.w);
        xr[i] = v;
    }
}

// ---------------- gating (proven) ----------------
__global__ void __launch_bounds__(256) gate_kernel(const float* __restrict__ x,
                                                   const float* __restrict__ wg) {
    __shared__ float swg[E_EXP][D_DIM];
    int tid = threadIdx.x;
    for (int i = tid; i < D_DIM * E_EXP; i += 256) {
        int d = i >> 3, e = i & 7;
        swg[e][d] = wg[i];
    }
    __syncthreads();

    int warp = tid >> 5, lane = tid & 31;
    int t = blockIdx.x * 8 + warp;
    const float* xr = x + (size_t)t * D_DIM;

    float acc[E_EXP];
#pragma unroll
    for (int e = 0; e < E_EXP; e++) acc[e] = 0.f;
    for (int d = lane; d < D_DIM; d += 32) {
        float xv = xr[d];
#pragma unroll
        for (int e = 0; e < E_EXP; e++) acc[e] = fmaf(xv, swg[e][d], acc[e]);
    }
#pragma unroll
    for (int e = 0; e < E_EXP; e++)
#pragma unroll
        for (int o = 16; o > 0; o >>= 1)
            acc[e] += __shfl_xor_sync(0xffffffffu, acc[e], o);

    if (lane == 0) {
        int e0 = 0; float l0 = acc[0];
#pragma unroll
        for (int e = 1; e < E_EXP; e++) if (acc[e] > l0) { l0 = acc[e]; e0 = e; }
        int e1 = -1; float l1 = -3.0e38f;
#pragma unroll
        for (int e = 0; e < E_EXP; e++) {
            if (e == e0) continue;
            if (acc[e] > l1) { l1 = acc[e]; e1 = e; }
        }
        float ex  = __expf(l1 - l0);
        float inv = 1.f / (1.f + ex);
        g_probs[2 * t]     = inv;
        g_probs[2 * t + 1] = ex * inv;
        int p0 = atomicAdd(&g_cnt[e0], 1);
        g_list[e0 * T_TOK + p0] = 2 * t;
        int p1 = atomicAdd(&g_cnt[e1], 1);
        g_list[e1 * T_TOK + p1] = 2 * t + 1;
    }
}

// ============= GEMM1a: g_Hs = silu(gather(xr) @ w1)  (gemm2 instruction mix) ==
__global__ void __launch_bounds__(256, 2) gemm1a_kernel(const float* __restrict__ xr,
                                                        const float* __restrict__ w1) {
    int e   = blockIdx.z;
    int n_e = g_cnt[e];
    int m0  = blockIdx.x * 128;
    if (m0 >= n_e) return;
    int f0  = blockIdx.y * 128;

    extern __shared__ char smem[];
    int* slots = (int*)smem;
    uint32_t sb = smem_u32(smem);
    int tid = threadIdx.x, wid = tid >> 5, lane = tid & 31;

    if (tid < 128) {
        int m = m0 + tid;
        slots[tid] = g_list[e * T_TOK + (m < n_e ? m : m0)];
    }
    __syncthreads();

    const float* W = w1 + (size_t)e * D_DIM * F_DIM + f0;

    auto issue = [&](int ci, int s) {
        int k0 = ci * 32;
        uint32_t base = sb + 1024 + s * (A_BYTES + B_BYTES);
#pragma unroll
        for (int it = 0; it < 4; it++) {
            int idx = it * 256 + tid;
            int row = idx >> 3, kq = idx & 7;
            const float* src = xr + (size_t)(slots[row] >> 1) * D_DIM + k0 + kq * 4;
            CP16(base + row * 144 + kq * 16, src);
        }
        uint32_t bb = base + A_BYTES;
#pragma unroll
        for (int it = 0; it < 4; it++) {
            int idx = it * 256 + tid;
            int kr = idx >> 5, nq = idx & 31;
            CP16(bb + kr * 544 + nq * 16, W + (size_t)(k0 + kr) * F_DIM + nq * 4);
        }
        CP_COMMIT();
    };

    issue(0, 0);
    issue(1, 1);

    int g = lane >> 2, t = lane & 3;
    int m0w = (wid & 1) * 64, n0w = (wid >> 1) * 32;

    float c[4][4][4];
#pragma unroll
    for (int a = 0; a < 4; a++)
#pragma unroll
        for (int b = 0; b < 4; b++)
#pragma unroll
            for (int r = 0; r < 4; r++) c[a][b][r] = 0.f;

    const int NCH = D_DIM / 32;  // 32
    int cur = 0, ibuf = 2;
    for (int ci = 0; ci < NCH; ci++) {
        CP_WAIT1();
        __syncthreads();
        if (ci + 2 < NCH) issue(ci + 2, ibuf); else CP_COMMIT();
        if (++ibuf == 3) ibuf = 0;

        const float* As = (const float*)(smem + 1024 + cur * (A_BYTES + B_BYTES));
        const float* Bs = As + A_BYTES / 4;
        if (++cur == 3) cur = 0;

#pragma unroll
        for (int kk = 0; kk < 4; kk++) {
            uint32_t af[4][4], bf[4][2];
#pragma unroll
            for (int mf = 0; mf < 4; mf++) {
                const float* ap = As + (m0w + mf * 16 + g) * AST + kk * 8 + t;
                af[mf][0] = __float_as_uint(ap[0]);
                af[mf][1] = __float_as_uint(ap[8 * AST]);
                af[mf][2] = __float_as_uint(ap[4]);
                af[mf][3] = __float_as_uint(ap[8 * AST + 4]);
            }
#pragma unroll
            for (int nf = 0; nf < 4; nf++) {
                const float* bp = Bs + (kk * 8 + t) * BST + n0w + nf * 8 + g;
                bf[nf][0] = lds_tf32(bp);
                bf[nf][1] = lds_tf32(bp + 4 * BST);
            }
#pragma unroll
            for (int mf = 0; mf < 4; mf++)
#pragma unroll
                for (int nf = 0; nf < 4; nf++)
                    MMA_TF32(c[mf][nf], af[mf], bf[nf]);
        }
    }

    // epilogue: store silu(c) exact fp32
#pragma unroll
    for (int mf = 0; mf < 4; mf++) {
#pragma unroll
        for (int half = 0; half < 2; half++) {
            int row = m0w + mf * 16 + g + 8 * half;
            if (m0 + row >= n_e) continue;
            float* hp = g_Hs + (size_t)slots[row] * F_DIM + f0;
#pragma unroll
            for (int nf = 0; nf < 4; nf++) {
                float v0 = c[mf][nf][2 * half + 0];
                float v1 = c[mf][nf][2 * half + 1];
                float2 o;
                o.x = v0 / (1.f + __expf(-v0));
                o.y = v1 / (1.f + __expf(-v1));
                *(float2*)(hp + n0w + nf * 8 + 2 * t) = o;
            }
        }
    }
}

// ============= GEMM1b: g_H = tf32(g_Hs * (gather(xr) @ w3)) ===================
__global__ void __launch_bounds__(256, 2) gemm1b_kernel(const float* __restrict__ xr,
                                                        const float* __restrict__ w3) {
    int e   = blockIdx.z;
    int n_e = g_cnt[e];
    int m0  = blockIdx.x * 128;
    if (m0 >= n_e) return;
    int f0  = blockIdx.y * 128;

    extern __shared__ char smem[];
    int* slots = (int*)smem;
    uint32_t sb = smem_u32(smem);
    int tid = threadIdx.x, wid = tid >> 5, lane = tid & 31;

    if (tid < 128) {
        int m = m0 + tid;
        slots[tid] = g_list[e * T_TOK + (m < n_e ? m : m0)];
    }
    __syncthreads();

    const float* W = w3 + (size_t)e * D_DIM * F_DIM + f0;

    auto issue = [&](int ci, int s) {
        int k0 = ci * 32;
        uint32_t base = sb + 1024 + s * (A_BYTES + B_BYTES);
#pragma unroll
        for (int it = 0; it < 4; it++) {
            int idx = it * 256 + tid;
            int row = idx >> 3, kq = idx & 7;
            const float* src = xr + (size_t)(slots[row] >> 1) * D_DIM + k0 + kq * 4;
            CP16(base + row * 144 + kq * 16, src);
        }
        uint32_t bb = base + A_BYTES;
#pragma unroll
        for (int it = 0; it < 4; it++) {
            int idx = it * 256 + tid;
            int kr = idx >> 5, nq = idx & 31;
            CP16(bb + kr * 544 + nq * 16, W + (size_t)(k0 + kr) * F_DIM + nq * 4);
        }
        CP_COMMIT();
    };

    issue(0, 0);
    issue(1, 1);

    int g = lane >> 2, t = lane & 3;
    int m0w = (wid & 1) * 64, n0w = (wid >> 1) * 32;

    float c[4][4][4];
#pragma unroll
    for (int a = 0; a < 4; a++)
#pragma unroll
        for (int b = 0; b < 4; b++)
#pragma unroll
            for (int r = 0; r < 4; r++) c[a][b][r] = 0.f;

    const int NCH = D_DIM / 32;  // 32
    int cur = 0, ibuf = 2;
    for (int ci = 0; ci < NCH; ci++) {
        CP_WAIT1();
        __syncthreads();
        if (ci + 2 < NCH) issue(ci + 2, ibuf); else CP_COMMIT();
        if (++ibuf == 3) ibuf = 0;

        const float* As = (const float*)(smem + 1024 + cur * (A_BYTES + B_BYTES));
        const float* Bs = As + A_BYTES / 4;
        if (++cur == 3) cur = 0;

#pragma unroll
        for (int kk = 0; kk < 4; kk++) {
            uint32_t af[4][4], bf[4][2];
#pragma unroll
            for (int mf = 0; mf < 4; mf++) {
                const float* ap = As + (m0w + mf * 16 + g) * AST + kk * 8 + t;
                af[mf][0] = __float_as_uint(ap[0]);
                af[mf][1] = __float_as_uint(ap[8 * AST]);
                af[mf][2] = __float_as_uint(ap[4]);
                af[mf][3] = __float_as_uint(ap[8 * AST + 4]);
            }
#pragma unroll
            for (int nf = 0; nf < 4; nf++) {
                const float* bp = Bs + (kk * 8 + t) * BST + n0w + nf * 8 + g;
                bf[nf][0] = lds_tf32(bp);
                bf[nf][1] = lds_tf32(bp + 4 * BST);
            }
#pragma unroll
            for (int mf = 0; mf < 4; mf++)
#pragma unroll
                for (int nf = 0; nf < 4; nf++)
                    MMA_TF32(c[mf][nf], af[mf], bf[nf]);
        }
    }

    // epilogue: H = rna_tf32(silu_stored * c3)
#pragma unroll
    for (int mf = 0; mf < 4; mf++) {
#pragma unroll
        for (int half = 0; half < 2; half++) {
            int row = m0w + mf * 16 + g + 8 * half;
            if (m0 + row >= n_e) continue;
            const float* sp = g_Hs + (size_t)slots[row] * F_DIM + f0;
            float* hp = g_H + (size_t)slots[row] * F_DIM + f0;
#pragma unroll
            for (int nf = 0; nf < 4; nf++) {
                float2 s = *(const float2*)(sp + n0w + nf * 8 + 2 * t);
                float2 o;
                o.x = to_tf32(s.x * c[mf][nf][2 * half + 0]);
                o.y = to_tf32(s.y * c[mf][nf][2 * half + 1]);
                *(float2*)(hp + n0w + nf * 8 + 2 * t) = o;
            }
        }
    }
}

// ======================= GEMM2: Y = H @ w2 (proven, untouched) ================
__global__ void __launch_bounds__(256, 2) gemm2_kernel(const float* __restrict__ w2) {
    int e   = blockIdx.z;
    int n_e = g_cnt[e];
    int m0  = blockIdx.x * 128;
    if (m0 >= n_e) return;
    int n0  = blockIdx.y * 128;

    extern __shared__ char smem[];
    int* slots = (int*)smem;
    uint32_t sb = smem_u32(smem);
    int tid = threadIdx.x, wid = tid >> 5, lane = tid & 31;

    if (tid < 128) {
        int m = m0 + tid;
        slots[tid] = g_list[e * T_TOK + (m < n_e ? m : m0)];
    }
    __syncthreads();

    const float* W2 = w2 + (size_t)e * F_DIM * D_DIM + n0;

    auto issue = [&](int ci, int s) {
        int k0 = ci * 32;
        uint32_t base = sb + 1024 + s * (A_BYTES + B_BYTES);
#pragma unroll
        for (int it = 0; it < 4; it++) {
            int idx = it * 256 + tid;
            int row = idx >> 3, kq = idx & 7;
            const float* src = g_H + (size_t)slots[row] * F_DIM + k0 + kq * 4;
            CP16(base + row * 144 + kq * 16, src);
        }
        uint32_t bb = base + A_BYTES;
#pragma unroll
        for (int it = 0; it < 4; it++) {
            int idx = it * 256 + tid;
            int kr = idx >> 5, nq = idx & 31;
            CP16(bb + kr * 544 + nq * 16, W2 + (size_t)(k0 + kr) * D_DIM + nq * 4);
        }
        CP_COMMIT();
    };

    issue(0, 0);
    issue(1, 1);

    int g = lane >> 2, t = lane & 3;
    int m0w = (wid & 1) * 64, n0w = (wid >> 1) * 32;

    float c[4][4][4];
#pragma unroll
    for (int a = 0; a < 4; a++)
#pragma unroll
        for (int b = 0; b < 4; b++)
#pragma unroll
            for (int r = 0; r < 4; r++) c[a][b][r] = 0.f;

    const int NCH = F_DIM / 32;  // 64
    int cur = 0, ibuf = 2;
    for (int ci = 0; ci < NCH; ci++) {
        CP_WAIT1();
        __syncthreads();
        if (ci + 2 < NCH) issue(ci + 2, ibuf); else CP_COMMIT();
        if (++ibuf == 3) ibuf = 0;

        const float* As = (const float*)(smem + 1024 + cur * (A_BYTES + B_BYTES));
        const float* Bs = As + A_BYTES / 4;
        if (++cur == 3) cur = 0;

#pragma unroll
        for (int kk = 0; kk < 4; kk++) {
            uint32_t af[4][4], bf[4][2];
#pragma unroll
            for (int mf = 0; mf < 4; mf++) {
                const float* ap = As + (m0w + mf * 16 + g) * AST + kk * 8 + t;
                af[mf][0] = __float_as_uint(ap[0]);
                af[mf][1] = __float_as_uint(ap[8 * AST]);
                af[mf][2] = __float_as_uint(ap[4]);
                af[mf][3] = __float_as_uint(ap[8 * AST + 4]);
            }
#pragma unroll
            for (int nf = 0; nf < 4; nf++) {
                const float* bp = Bs + (kk * 8 + t) * BST + n0w + nf * 8 + g;
                bf[nf][0] = lds_tf32(bp);
                bf[nf][1] = lds_tf32(bp + 4 * BST);
            }
#pragma unroll
            for (int mf = 0; mf < 4; mf++)
#pragma unroll
                for (int nf = 0; nf < 4; nf++)
                    MMA_TF32(c[mf][nf], af[mf], bf[nf]);
        }
    }

#pragma unroll
    for (int mf = 0; mf < 4; mf++) {
#pragma unroll
        for (int half = 0; half < 2; half++) {
            int row = m0w + mf * 16 + g + 8 * half;
            if (m0 + row >= n_e) continue;
            float* yp = g_Y + (size_t)slots[row] * D_DIM + n0;
#pragma unroll
            for (int nf = 0; nf < 4; nf++) {
                float2 o;
                o.x = c[mf][nf][2 * half + 0];
                o.y = c[mf][nf][2 * half + 1];
                *(float2*)(yp + n0w + nf * 8 + 2 * t) = o;
            }
        }
    }
}

// ---------------- combine ----------------
__global__ void __launch_bounds__(256) combine_kernel(float* __restrict__ out) {
    int idx = blockIdx.x * 256 + threadIdx.x;
    int t   = idx / (D_DIM / 4);
    int d4  = idx % (D_DIM / 4);
    float p0 = g_probs[2 * t], p1 = g_probs[2 * t + 1];
    const float4* y0 = (const float4*)(g_Y + (size_t)(2 * t) * D_DIM) + d4;
    const float4* y1 = (const float4*)(g_Y + (size_t)(2 * t + 1) * D_DIM) + d4;
    float4 a = *y0, b = *y1, o;
    o.x = p0 * a.x + p1 * b.x;
    o.y = p0 * a.y + p1 * b.y;
    o.z = p0 * a.z + p1 * b.z;
    o.w = p0 * a.w + p1 * b.w;
    *((float4*)(out + (size_t)t * D_DIM) + d4) = o;
}

// ---------------- launch ----------------
extern "C" void kernel_launch(void* const* d_in, const int* in_sizes, int n_in,
                              void* d_out, int out_size) {
    const float* x  = (const float*)d_in[0];
    const float* wg = (const float*)d_in[1];
    const float* w1 = (const float*)d_in[2];
    const float* w3 = (const float*)d_in[3];
    const float* w2 = (const float*)d_in[4];
    float* out = (float*)d_out;

    const int SMEM_G = 1024 + 3 * (A_BYTES + B_BYTES);  // 108544
    cudaFuncSetAttribute(gemm1a_kernel, cudaFuncAttributeMaxDynamicSharedMemorySize, SMEM_G);
    cudaFuncSetAttribute(gemm1b_kernel, cudaFuncAttributeMaxDynamicSharedMemorySize, SMEM_G);
    cudaFuncSetAttribute(gemm2_kernel,  cudaFuncAttributeMaxDynamicSharedMemorySize, SMEM_G);

    float* xr;
    cudaGetSymbolAddress((void**)&xr, g_xr);

    init_kernel<<<1, 32>>>();
    round_x_kernel<<<2048, 256>>>((const float4*)x, (float4*)xr);
    gate_kernel<<<T_TOK / 8, 256>>>(x, wg);
    gemm1a_kernel<<<dim3(T_TOK / 128, F_DIM / 128, E_EXP), 256, SMEM_G>>>(xr, w1);
    gemm1b_kernel<<<dim3(T_TOK / 128, F_DIM / 128, E_EXP), 256, SMEM_G>>>(xr, w3);
    gemm2_kernel<<<dim3(T_TOK / 128, D_DIM / 128, E_EXP), 256, SMEM_G>>>(w2);
    combine_kernel<<<(T_TOK * D_DIM / 4) / 256, 256>>>(out);
}

// round 11
// speedup vs baseline: 1.1133x; 1.0435x over previous
#include <cuda_runtime.h>
#include <cstdint>

#define T_TOK 8192
#define D_DIM 1024
#define E_EXP 8
#define F_DIM 2048
#define NSLOT (2 * T_TOK)

// ---------------- device-global scratch ----------------
__device__ int   g_cnt[E_EXP];
__device__ int   g_list[E_EXP * T_TOK];
__device__ float g_probs[NSLOT];
__device__ float g_xr[(size_t)T_TOK * D_DIM];  // tf32-rounded x
__device__ float g_Hs[(size_t)NSLOT * F_DIM];  // silu(x@w1), exact fp32
__device__ float g_H[(size_t)NSLOT * F_DIM];   // tf32-rounded silu*C3
__device__ float g_Y[(size_t)NSLOT * D_DIM];

// ---------------- helpers ----------------
__device__ __forceinline__ uint32_t smem_u32(const void* p) {
    uint32_t a;
    asm("{ .reg .u64 t; cvta.to.shared.u64 t, %1; cvt.u32.u64 %0, t; }" : "=r"(a) : "l"(p));
    return a;
}
__device__ __forceinline__ float to_tf32(float x) {
    uint32_t r;
    asm("cvt.rna.tf32.f32 %0, %1;" : "=r"(r) : "f"(x));
    return __uint_as_float(r);
}
__device__ __forceinline__ uint32_t lds_tf32(const float* p) {
    uint32_t r;
    asm("cvt.rna.tf32.f32 %0, %1;" : "=r"(r) : "f"(*p));
    return r;
}
#define CP16(dst, src) asm volatile("cp.async.cg.shared.global [%0], [%1], 16;" :: "r"(dst), "l"(src))

// mbarrier pipeline primitives (sm_80/90 baseline PTX)
// NOTE: .noinc is load-bearing — the default form pre-increments the expected
// count and nets to zero against the init count (R10 deadlock).
#define MBAR_INIT(mb, c)  asm volatile("mbarrier.init.shared.b64 [%0], %1;" :: "r"(mb), "r"((uint32_t)(c)) : "memory")
#define MBAR_ARRIVE(mb)   asm volatile("mbarrier.arrive.shared.b64 _, [%0];" :: "r"(mb) : "memory")
#define CPMBAR_ARRIVE(mb) asm volatile("cp.async.mbarrier.arrive.noinc.shared.b64 [%0];" :: "r"(mb) : "memory")
__device__ __forceinline__ void mbar_wait(uint32_t mb, uint32_t parity) {
    uint32_t done;
    do {
        asm volatile("{ .reg .pred p; mbarrier.try_wait.parity.shared.b64 p, [%1], %2; selp.b32 %0, 1, 0, p; }"
                     : "=r"(done) : "r"(mb), "r"(parity) : "memory");
    } while (!done);
}

#define MMA_TF32(c, a, b)                                                          \
    asm volatile("mma.sync.aligned.m16n8k8.row.col.f32.tf32.tf32.f32 "             \
                 "{%0,%1,%2,%3}, {%4,%5,%6,%7}, {%8,%9}, {%0,%1,%2,%3};"           \
                 : "+f"((c)[0]), "+f"((c)[1]), "+f"((c)[2]), "+f"((c)[3])          \
                 : "r"((a)[0]), "r"((a)[1]), "r"((a)[2]), "r"((a)[3]),             \
                   "r"((b)[0]), "r"((b)[1]))

// smem strides (floats): A rows padded to 36 (144B), B rows padded to 136 (544B)
#define AST 36
#define BST 136
#define A_BYTES (128 * AST * 4)   // 18432
#define B_BYTES (32 * BST * 4)    // 17408
// smem map: [0..512) slots, [512..560) mbarriers (3 full @512+8s, 3 empty @536+8s), tiles @1024
#define MBF(sb, s) ((sb) + 512 + (s) * 8)
#define MBE(sb, s) ((sb) + 536 + (s) * 8)

// ---------------- init ----------------
__global__ void init_kernel() {
    if (threadIdx.x < E_EXP) g_cnt[threadIdx.x] = 0;
}

// ---------------- pre-round x to tf32 (32 MB only) ----------------
__global__ void __launch_bounds__(256) round_x_kernel(const float4* __restrict__ x,
                                                      float4* __restrict__ xr) {
    int i = blockIdx.x * 256 + threadIdx.x;
    const int n4 = T_TOK * D_DIM / 4;
    int stride = gridDim.x * 256;
    for (; i < n4; i += stride) {
        float4 v = x[i];
        v.x = to_tf32(v.x); v.y = to_tf32(v.y);
        v.z = to_tf32(v.z); v.w = to_tf32(v.w);
        xr[i] = v;
    }
}

// ---------------- gating (proven) ----------------
__global__ void __launch_bounds__(256) gate_kernel(const float* __restrict__ x,
                                                   const float* __restrict__ wg) {
    __shared__ float swg[E_EXP][D_DIM];
    int tid = threadIdx.x;
    for (int i = tid; i < D_DIM * E_EXP; i += 256) {
        int d = i >> 3, e = i & 7;
        swg[e][d] = wg[i];
    }
    __syncthreads();

    int warp = tid >> 5, lane = tid & 31;
    int t = blockIdx.x * 8 + warp;
    const float* xr = x + (size_t)t * D_DIM;

    float acc[E_EXP];
#pragma unroll
    for (int e = 0; e < E_EXP; e++) acc[e] = 0.f;
    for (int d = lane; d < D_DIM; d += 32) {
        float xv = xr[d];
#pragma unroll
        for (int e = 0; e < E_EXP; e++) acc[e] = fmaf(xv, swg[e][d], acc[e]);
    }
#pragma unroll
    for (int e = 0; e < E_EXP; e++)
#pragma unroll
        for (int o = 16; o > 0; o >>= 1)
            acc[e] += __shfl_xor_sync(0xffffffffu, acc[e], o);

    if (lane == 0) {
        int e0 = 0; float l0 = acc[0];
#pragma unroll
        for (int e = 1; e < E_EXP; e++) if (acc[e] > l0) { l0 = acc[e]; e0 = e; }
        int e1 = -1; float l1 = -3.0e38f;
#pragma unroll
        for (int e = 0; e < E_EXP; e++) {
            if (e == e0) continue;
            if (acc[e] > l1) { l1 = acc[e]; e1 = e; }
        }
        float ex  = __expf(l1 - l0);
        float inv = 1.f / (1.f + ex);
        g_probs[2 * t]     = inv;
        g_probs[2 * t + 1] = ex * inv;
        int p0 = atomicAdd(&g_cnt[e0], 1);
        g_list[e0 * T_TOK + p0] = 2 * t;
        int p1 = atomicAdd(&g_cnt[e1], 1);
        g_list[e1 * T_TOK + p1] = 2 * t + 1;
    }
}

// ============= GEMM1a: g_Hs = silu(gather(xr) @ w1), mbarrier pipeline ========
__global__ void __launch_bounds__(256, 2) gemm1a_kernel(const float* __restrict__ xr,
                                                        const float* __restrict__ w1) {
    int e   = blockIdx.z;
    int n_e = g_cnt[e];
    int m0  = blockIdx.x * 128;
    if (m0 >= n_e) return;
    int f0  = blockIdx.y * 128;

    extern __shared__ char smem[];
    int* slots = (int*)smem;
    uint32_t sb = smem_u32(smem);
    int tid = threadIdx.x, wid = tid >> 5, lane = tid & 31;

    if (tid < 128) {
        int m = m0 + tid;
        slots[tid] = g_list[e * T_TOK + (m < n_e ? m : m0)];
    }
    if (tid == 0) {
#pragma unroll
        for (int s = 0; s < 3; s++) { MBAR_INIT(MBF(sb, s), 256); MBAR_INIT(MBE(sb, s), 256); }
    }
    __syncthreads();

    const float* W = w1 + (size_t)e * D_DIM * F_DIM + f0;

    auto issue = [&](int ci, int s) {
        int k0 = ci * 32;
        uint32_t base = sb + 1024 + s * (A_BYTES + B_BYTES);
#pragma unroll
        for (int it = 0; it < 4; it++) {
            int idx = it * 256 + tid;
            int row = idx >> 3, kq = idx & 7;
            const float* src = xr + (size_t)(slots[row] >> 1) * D_DIM + k0 + kq * 4;
            CP16(base + row * 144 + kq * 16, src);
        }
        uint32_t bb = base + A_BYTES;
#pragma unroll
        for (int it = 0; it < 4; it++) {
            int idx = it * 256 + tid;
            int kr = idx >> 5, nq = idx & 31;
            CP16(bb + kr * 544 + nq * 16, W + (size_t)(k0 + kr) * F_DIM + nq * 4);
        }
    };

    issue(0, 0); CPMBAR_ARRIVE(MBF(sb, 0));
    issue(1, 1); CPMBAR_ARRIVE(MBF(sb, 1));

    int g = lane >> 2, t = lane & 3;
    int m0w = (wid & 1) * 64, n0w = (wid >> 1) * 32;

    float c[4][4][4];
#pragma unroll
    for (int a = 0; a < 4; a++)
#pragma unroll
        for (int b = 0; b < 4; b++)
#pragma unroll
            for (int r = 0; r < 4; r++) c[a][b][r] = 0.f;

    const int NCH = D_DIM / 32;  // 32
    int cs = 0, ck = 0;          // consumer stage, parity
    int ps = 2, pk = 0;          // producer stage, reuse count
    for (int ci = 0; ci < NCH; ci++) {
        if (ci + 2 < NCH) {
            if (pk) mbar_wait(MBE(sb, ps), (pk - 1) & 1);
            issue(ci + 2, ps);
            CPMBAR_ARRIVE(MBF(sb, ps));
            if (++ps == 3) { ps = 0; ++pk; }
        }
        mbar_wait(MBF(sb, cs), ck);

        const float* As = (const float*)(smem + 1024 + cs * (A_BYTES + B_BYTES));
        const float* Bs = As + A_BYTES / 4;

#pragma unroll
        for (int kk = 0; kk < 4; kk++) {
            uint32_t af[4][4], bf[4][2];
#pragma unroll
            for (int mf = 0; mf < 4; mf++) {
                const float* ap = As + (m0w + mf * 16 + g) * AST + kk * 8 + t;
                af[mf][0] = __float_as_uint(ap[0]);
                af[mf][1] = __float_as_uint(ap[8 * AST]);
                af[mf][2] = __float_as_uint(ap[4]);
                af[mf][3] = __float_as_uint(ap[8 * AST + 4]);
            }
#pragma unroll
            for (int nf = 0; nf < 4; nf++) {
                const float* bp = Bs + (kk * 8 + t) * BST + n0w + nf * 8 + g;
                bf[nf][0] = lds_tf32(bp);
                bf[nf][1] = lds_tf32(bp + 4 * BST);
            }
#pragma unroll
            for (int mf = 0; mf < 4; mf++)
#pragma unroll
                for (int nf = 0; nf < 4; nf++)
                    MMA_TF32(c[mf][nf], af[mf], bf[nf]);
        }
        MBAR_ARRIVE(MBE(sb, cs));
        if (++cs == 3) { cs = 0; ck ^= 1; }
    }

    // epilogue: store silu(c) exact fp32
#pragma unroll
    for (int mf = 0; mf < 4; mf++) {
#pragma unroll
        for (int half = 0; half < 2; half++) {
            int row = m0w + mf * 16 + g + 8 * half;
            if (m0 + row >= n_e) continue;
            float* hp = g_Hs + (size_t)slots[row] * F_DIM + f0;
#pragma unroll
            for (int nf = 0; nf < 4; nf++) {
                float v0 = c[mf][nf][2 * half + 0];
                float v1 = c[mf][nf][2 * half + 1];
                float2 o;
                o.x = v0 / (1.f + __expf(-v0));
                o.y = v1 / (1.f + __expf(-v1));
                *(float2*)(hp + n0w + nf * 8 + 2 * t) = o;
            }
        }
    }
}

// ============= GEMM1b: g_H = tf32(g_Hs * (gather(xr) @ w3)), mbarrier =========
__global__ void __launch_bounds__(256, 2) gemm1b_kernel(const float* __restrict__ xr,
                                                        const float* __restrict__ w3) {
    int e   = blockIdx.z;
    int n_e = g_cnt[e];
    int m0  = blockIdx.x * 128;
    if (m0 >= n_e) return;
    int f0  = blockIdx.y * 128;

    extern __shared__ char smem[];
    int* slots = (int*)smem;
    uint32_t sb = smem_u32(smem);
    int tid = threadIdx.x, wid = tid >> 5, lane = tid & 31;

    if (tid < 128) {
        int m = m0 + tid;
        slots[tid] = g_list[e * T_TOK + (m < n_e ? m : m0)];
    }
    if (tid == 0) {
#pragma unroll
        for (int s = 0; s < 3; s++) { MBAR_INIT(MBF(sb, s), 256); MBAR_INIT(MBE(sb, s), 256); }
    }
    __syncthreads();

    const float* W = w3 + (size_t)e * D_DIM * F_DIM + f0;

    auto issue = [&](int ci, int s) {
        int k0 = ci * 32;
        uint32_t base = sb + 1024 + s * (A_BYTES + B_BYTES);
#pragma unroll
        for (int it = 0; it < 4; it++) {
            int idx = it * 256 + tid;
            int row = idx >> 3, kq = idx & 7;
            const float* src = xr + (size_t)(slots[row] >> 1) * D_DIM + k0 + kq * 4;
            CP16(base + row * 144 + kq * 16, src);
        }
        uint32_t bb = base + A_BYTES;
#pragma unroll
        for (int it = 0; it < 4; it++) {
            int idx = it * 256 + tid;
            int kr = idx >> 5, nq = idx & 31;
            CP16(bb + kr * 544 + nq * 16, W + (size_t)(k0 + kr) * F_DIM + nq * 4);
        }
    };

    issue(0, 0); CPMBAR_ARRIVE(MBF(sb, 0));
    issue(1, 1); CPMBAR_ARRIVE(MBF(sb, 1));

    int g = lane >> 2, t = lane & 3;
    int m0w = (wid & 1) * 64, n0w = (wid >> 1) * 32;

    float c[4][4][4];
#pragma unroll
    for (int a = 0; a < 4; a++)
#pragma unroll
        for (int b = 0; b < 4; b++)
#pragma unroll
            for (int r = 0; r < 4; r++) c[a][b][r] = 0.f;

    const int NCH = D_DIM / 32;  // 32
    int cs = 0, ck = 0;
    int ps = 2, pk = 0;
    for (int ci = 0; ci < NCH; ci++) {
        if (ci + 2 < NCH) {
            if (pk) mbar_wait(MBE(sb, ps), (pk - 1) & 1);
            issue(ci + 2, ps);
            CPMBAR_ARRIVE(MBF(sb, ps));
            if (++ps == 3) { ps = 0; ++pk; }
        }
        mbar_wait(MBF(sb, cs), ck);

        const float* As = (const float*)(smem + 1024 + cs * (A_BYTES + B_BYTES));
        const float* Bs = As + A_BYTES / 4;

#pragma unroll
        for (int kk = 0; kk < 4; kk++) {
            uint32_t af[4][4], bf[4][2];
#pragma unroll
            for (int mf = 0; mf < 4; mf++) {
                const float* ap = As + (m0w + mf * 16 + g) * AST + kk * 8 + t;
                af[mf][0] = __float_as_uint(ap[0]);
                af[mf][1] = __float_as_uint(ap[8 * AST]);
                af[mf][2] = __float_as_uint(ap[4]);
                af[mf][3] = __float_as_uint(ap[8 * AST + 4]);
            }
#pragma unroll
            for (int nf = 0; nf < 4; nf++) {
                const float* bp = Bs + (kk * 8 + t) * BST + n0w + nf * 8 + g;
                bf[nf][0] = lds_tf32(bp);
                bf[nf][1] = lds_tf32(bp + 4 * BST);
            }
#pragma unroll
            for (int mf = 0; mf < 4; mf++)
#pragma unroll
                for (int nf = 0; nf < 4; nf++)
                    MMA_TF32(c[mf][nf], af[mf], bf[nf]);
        }
        MBAR_ARRIVE(MBE(sb, cs));
        if (++cs == 3) { cs = 0; ck ^= 1; }
    }

    // epilogue: H = rna_tf32(silu_stored * c3)
#pragma unroll
    for (int mf = 0; mf < 4; mf++) {
#pragma unroll
        for (int half = 0; half < 2; half++) {
            int row = m0w + mf * 16 + g + 8 * half;
            if (m0 + row >= n_e) continue;
            const float* sp = g_Hs + (size_t)slots[row] * F_DIM + f0;
            float* hp = g_H + (size_t)slots[row] * F_DIM + f0;
#pragma unroll
            for (int nf = 0; nf < 4; nf++) {
                float2 s = *(const float2*)(sp + n0w + nf * 8 + 2 * t);
                float2 o;
                o.x = to_tf32(s.x * c[mf][nf][2 * half + 0]);
                o.y = to_tf32(s.y * c[mf][nf][2 * half + 1]);
                *(float2*)(hp + n0w + nf * 8 + 2 * t) = o;
            }
        }
    }
}

// ======================= GEMM2: Y = H @ w2, mbarrier pipeline =================
__global__ void __launch_bounds__(256, 2) gemm2_kernel(const float* __restrict__ w2) {
    int e   = blockIdx.z;
    int n_e = g_cnt[e];
    int m0  = blockIdx.x * 128;
    if (m0 >= n_e) return;
    int n0  = blockIdx.y * 128;

    extern __shared__ char smem[];
    int* slots = (int*)smem;
    uint32_t sb = smem_u32(smem);
    int tid = threadIdx.x, wid = tid >> 5, lane = tid & 31;

    if (tid < 128) {
        int m = m0 + tid;
        slots[tid] = g_list[e * T_TOK + (m < n_e ? m : m0)];
    }
    if (tid == 0) {
#pragma unroll
        for (int s = 0; s < 3; s++) { MBAR_INIT(MBF(sb, s), 256); MBAR_INIT(MBE(sb, s), 256); }
    }
    __syncthreads();

    const float* W2 = w2 + (size_t)e * F_DIM * D_DIM + n0;

    auto issue = [&](int ci, int s) {
        int k0 = ci * 32;
        uint32_t base = sb + 1024 + s * (A_BYTES + B_BYTES);
#pragma unroll
        for (int it = 0; it < 4; it++) {
            int idx = it * 256 + tid;
            int row = idx >> 3, kq = idx & 7;
            const float* src = g_H + (size_t)slots[row] * F_DIM + k0 + kq * 4;
            CP16(base + row * 144 + kq * 16, src);
        }
        uint32_t bb = base + A_BYTES;
#pragma unroll
        for (int it = 0; it < 4; it++) {
            int idx = it * 256 + tid;
            int kr = idx >> 5, nq = idx & 31;
            CP16(bb + kr * 544 + nq * 16, W2 + (size_t)(k0 + kr) * D_DIM + nq * 4);
        }
    };

    issue(0, 0); CPMBAR_ARRIVE(MBF(sb, 0));
    issue(1, 1); CPMBAR_ARRIVE(MBF(sb, 1));

    int g = lane >> 2, t = lane & 3;
    int m0w = (wid & 1) * 64, n0w = (wid >> 1) * 32;

    float c[4][4][4];
#pragma unroll
    for (int a = 0; a < 4; a++)
#pragma unroll
        for (int b = 0; b < 4; b++)
#pragma unroll
            for (int r = 0; r < 4; r++) c[a][b][r] = 0.f;

    const int NCH = F_DIM / 32;  // 64
    int cs = 0, ck = 0;
    int ps = 2, pk = 0;
    for (int ci = 0; ci < NCH; ci++) {
        if (ci + 2 < NCH) {
            if (pk) mbar_wait(MBE(sb, ps), (pk - 1) & 1);
            issue(ci + 2, ps);
            CPMBAR_ARRIVE(MBF(sb, ps));
            if (++ps == 3) { ps = 0; ++pk; }
        }
        mbar_wait(MBF(sb, cs), ck);

        const float* As = (const float*)(smem + 1024 + cs * (A_BYTES + B_BYTES));
        const float* Bs = As + A_BYTES / 4;

#pragma unroll
        for (int kk = 0; kk < 4; kk++) {
            uint32_t af[4][4], bf[4][2];
#pragma unroll
            for (int mf = 0; mf < 4; mf++) {
                const float* ap = As + (m0w + mf * 16 + g) * AST + kk * 8 + t;
                af[mf][0] = __float_as_uint(ap[0]);
                af[mf][1] = __float_as_uint(ap[8 * AST]);
                af[mf][2] = __float_as_uint(ap[4]);
                af[mf][3] = __float_as_uint(ap[8 * AST + 4]);
            }
#pragma unroll
            for (int nf = 0; nf < 4; nf++) {
                const float* bp = Bs + (kk * 8 + t) * BST + n0w + nf * 8 + g;
                bf[nf][0] = lds_tf32(bp);
                bf[nf][1] = lds_tf32(bp + 4 * BST);
            }
#pragma unroll
            for (int mf = 0; mf < 4; mf++)
#pragma unroll
                for (int nf = 0; nf < 4; nf++)
                    MMA_TF32(c[mf][nf], af[mf], bf[nf]);
        }
        MBAR_ARRIVE(MBE(sb, cs));
        if (++cs == 3) { cs = 0; ck ^= 1; }
    }

#pragma unroll
    for (int mf = 0; mf < 4; mf++) {
#pragma unroll
        for (int half = 0; half < 2; half++) {
            int row = m0w + mf * 16 + g + 8 * half;
            if (m0 + row >= n_e) continue;
            float* yp = g_Y + (size_t)slots[row] * D_DIM + n0;
#pragma unroll
            for (int nf = 0; nf < 4; nf++) {
                float2 o;
                o.x = c[mf][nf][2 * half + 0];
                o.y = c[mf][nf][2 * half + 1];
                *(float2*)(yp + n0w + nf * 8 + 2 * t) = o;
            }
        }
    }
}

// ---------------- combine ----------------
__global__ void __launch_bounds__(256) combine_kernel(float* __restrict__ out) {
    int idx = blockIdx.x * 256 + threadIdx.x;
    int t   = idx / (D_DIM / 4);
    int d4  = idx % (D_DIM / 4);
    float p0 = g_probs[2 * t], p1 = g_probs[2 * t + 1];
    const float4* y0 = (const float4*)(g_Y + (size_t)(2 * t) * D_DIM) + d4;
    const float4* y1 = (const float4*)(g_Y + (size_t)(2 * t + 1) * D_DIM) + d4;
    float4 a = *y0, b = *y1, o;
    o.x = p0 * a.x + p1 * b.x;
    o.y = p0 * a.y + p1 * b.y;
    o.z = p0 * a.z + p1 * b.z;
    o.w = p0 * a.w + p1 * b.w;
    *((float4*)(out + (size_t)t * D_DIM) + d4) = o;
}

// ---------------- launch ----------------
extern "C" void kernel_launch(void* const* d_in, const int* in_sizes, int n_in,
                              void* d_out, int out_size) {
    const float* x  = (const float*)d_in[0];
    const float* wg = (const float*)d_in[1];
    const float* w1 = (const float*)d_in[2];
    const float* w3 = (const float*)d_in[3];
    const float* w2 = (const float*)d_in[4];
    float* out = (float*)d_out;

    const int SMEM_G = 1024 + 3 * (A_BYTES + B_BYTES);  // 108544
    cudaFuncSetAttribute(gemm1a_kernel, cudaFuncAttributeMaxDynamicSharedMemorySize, SMEM_G);
    cudaFuncSetAttribute(gemm1b_kernel, cudaFuncAttributeMaxDynamicSharedMemorySize, SMEM_G);
    cudaFuncSetAttribute(gemm2_kernel,  cudaFuncAttributeMaxDynamicSharedMemorySize, SMEM_G);

    float* xr;
    cudaGetSymbolAddress((void**)&xr, g_xr);

    init_kernel<<<1, 32>>>();
    round_x_kernel<<<2048, 256>>>((const float4*)x, (float4*)xr);
    gate_kernel<<<T_TOK / 8, 256>>>(x, wg);
    gemm1a_kernel<<<dim3(T_TOK / 128, F_DIM / 128, E_EXP), 256, SMEM_G>>>(xr, w1);
    gemm1b_kernel<<<dim3(T_TOK / 128, F_DIM / 128, E_EXP), 256, SMEM_G>>>(xr, w3);
    gemm2_kernel<<<dim3(T_TOK / 128, D_DIM / 128, E_EXP), 256, SMEM_G>>>(w2);
    combine_kernel<<<(T_TOK * D_DIM / 4) / 256, 256>>>(out);
}